// round 6
// baseline (speedup 1.0000x reference)
#include <cuda_runtime.h>

#define NQ  8
#define DIM 256
#define SQ2 0.70710678118654752f

__device__ float2 g_psi[DIM];

__device__ __constant__ unsigned char PI_[28] =
    {0,0,0,0,0,0,0,1,1,1,1,1,1,2,2,2,2,2,3,3,3,3,4,4,4,5,5,6};
__device__ __constant__ unsigned char PJ_[28] =
    {1,2,3,4,5,6,7,2,3,4,5,6,7,3,4,5,6,7,4,5,6,7,5,6,7,6,7,7};

// ising fusion groups: (i, j1, j2) with j2 == 255 meaning single
__device__ __constant__ unsigned char GI_[16]  = {0,0,0,0,1,1,1,2,2,2,3,3,4,4,5,6};
__device__ __constant__ unsigned char GJ1_[16] = {1,3,5,7,2,4,6,3,5,7,4,6,5,7,6,7};
__device__ __constant__ unsigned char GJ2_[16] = {2,4,6,255,3,5,7,4,6,255,5,7,6,255,7,255};

__device__ __forceinline__ float2 cmul(float2 a, float2 b) {
    return make_float2(a.x * b.x - a.y * b.y, a.x * b.y + a.y * b.x);
}
__device__ __forceinline__ float2 cadd(float2 a, float2 b) {
    return make_float2(a.x + b.x, a.y + b.y);
}
__device__ __forceinline__ float2 cmad(float2 acc, float2 a, float2 b) {
    return make_float2(acc.x + a.x * b.x - a.y * b.y,
                       acc.y + a.x * b.y + a.y * b.x);
}

// ---------------------------------------------------------------------------
// Fully fused kernel: evolve + outer-product(real). 1 block, 256 threads.
// ---------------------------------------------------------------------------
__global__ void __launch_bounds__(256, 1)
fused_kernel(const float* __restrict__ x,
             const float* __restrict__ w,
             const float* __restrict__ cplg,
             float4* __restrict__ out,
             int write_out) {
    __shared__ float2 buf[2][DIM];
    __shared__ float2 pairM[28][16];
    __shared__ float  sw[210];
    __shared__ float  scpl[64];
    __shared__ float  red[8];

    const int tid = threadIdx.x;

    if (tid < 210) sw[tid]   = w[tid];
    if (tid < 64)  scpl[tid] = cplg[tid];
    const float xv = x[tid];

    float ss = xv * xv;
#pragma unroll
    for (int o = 16; o; o >>= 1) ss += __shfl_xor_sync(0xffffffffu, ss, o);
    if ((tid & 31) == 0) red[tid >> 5] = ss;
    __syncthreads();
    const float inv = rsqrtf(red[0] + red[1] + red[2] + red[3] +
                             red[4] + red[5] + red[6] + red[7]);

    // adjacency bitmask (uniform across threads)
    unsigned amask = 0;
    {
        float cmin = scpl[0], cmax = scpl[0];
#pragma unroll 1
        for (int i = 1; i < 64; i++) {
            const float c = scpl[i];
            cmin = fminf(cmin, c);
            cmax = fmaxf(cmax, c);
        }
        const float range = cmax - cmin;
#pragma unroll 1
        for (int p = 0; p < 28; p++) {
            const float cv = scpl[PI_[p] * 8 + PJ_[p]];
            if ((cv - cmin) / range > 0.5f) amask |= 1u << p;
        }
    }

    // build fused conv+pool 4x4 per pair: thread (p*4+col) owns one column
    if (tid < 112) {
        const int p   = tid >> 2;
        const int col = tid & 3;
        const int widx = 3 * NQ + 6 * __popc(amask & ((1u << p) - 1u));

        float2 v0 = make_float2(col == 0 ? 1.f : 0.f, 0.f);
        float2 v1 = make_float2(col == 1 ? 1.f : 0.f, 0.f);
        float2 v2 = make_float2(col == 2 ? 1.f : 0.f, 0.f);
        float2 v3 = make_float2(col == 3 ? 1.f : 0.f, 0.f);

#define PHASE_I(er, ei) { const float2 e = make_float2(er, ei), ec = make_float2(er, -(ei)); \
        v0 = cmul(v0, e); v1 = cmul(v1, e); v2 = cmul(v2, ec); v3 = cmul(v3, ec); }
#define PHASE_J(er, ei) { const float2 e = make_float2(er, ei), ec = make_float2(er, -(ei)); \
        v0 = cmul(v0, e); v1 = cmul(v1, ec); v2 = cmul(v2, e); v3 = cmul(v3, ec); }
#define RY_J(c, s) { float2 t; \
        t  = make_float2((c)*v0.x - (s)*v1.x, (c)*v0.y - (s)*v1.y); \
        v1 = make_float2((s)*v0.x + (c)*v1.x, (s)*v0.y + (c)*v1.y); v0 = t; \
        t  = make_float2((c)*v2.x - (s)*v3.x, (c)*v2.y - (s)*v3.y); \
        v3 = make_float2((s)*v2.x + (c)*v3.x, (s)*v2.y + (c)*v3.y); v2 = t; }
#define SWAP13 { const float2 t = v1; v1 = v3; v3 = t; }
#define SWAP23 { const float2 t = v2; v2 = v3; v3 = t; }

        float s0, c0, s1, c1, s2, c2, s3, c3, s4, c4, s5, c5;
        __sincosf(0.5f * sw[widx + 0], &s0, &c0);
        __sincosf(0.5f * sw[widx + 1], &s1, &c1);
        __sincosf(0.5f * sw[widx + 2], &s2, &c2);
        __sincosf(0.5f * sw[widx + 3], &s3, &c3);
        __sincosf(0.5f * sw[widx + 4], &s4, &c4);
        __sincosf(0.5f * sw[widx + 5], &s5, &c5);

        PHASE_J(SQ2,  SQ2);
        SWAP13;
        PHASE_I(c0, -s0);
        RY_J(c1, s1);
        SWAP23;
        RY_J(c2, s2);
        SWAP13;
        PHASE_I(SQ2, -SQ2);
        PHASE_J(SQ2,  SQ2);
        SWAP13;
        PHASE_I(c3, -s3);
        RY_J(c4, s4);
        SWAP23;
        RY_J(c5, s5);

        pairM[p][0 * 4 + col] = v0;
        pairM[p][1 * 4 + col] = v1;
        pairM[p][2 * 4 + col] = v2;
        pairM[p][3 * 4 + col] = v3;
#undef PHASE_I
#undef PHASE_J
#undef RY_J
#undef SWAP13
#undef SWAP23
    }

    buf[0][tid] = make_float2(xv * inv, 0.f);
    __syncthreads();

    int cp = 0;   // current parity

    // ---- fused single-qubit gates, two qubits per step (4 steps)
#pragma unroll 1
    for (int g = 0; g < 4; g++) {
        const int qa = 2 * g, qb = 2 * g + 1;
        float sxa, cxa, sya, cya, sza, cza;
        float sxb, cxb, syb, cyb, szb, czb;
        __sincosf(0.5f * sw[qa],      &sxa, &cxa);
        __sincosf(0.5f * sw[qa + 8],  &sya, &cya);
        __sincosf(0.5f * sw[qa + 16], &sza, &cza);
        __sincosf(0.5f * sw[qb],      &sxb, &cxb);
        __sincosf(0.5f * sw[qb + 8],  &syb, &cyb);
        __sincosf(0.5f * sw[qb + 16], &szb, &czb);

        // u = Rz * Ry * Rx for each qubit
        const float2 a_m00 = make_float2(cya * cxa,  sya * sxa);   // ry00*rx00 + ry01*rx01
        const float2 a_m01 = make_float2(-sya * cxa, -cya * sxa);  // wait careful below
        // Recompute carefully:
        // Rx = [[cx, -i sx],[-i sx, cx]], Ry = [[cy, -sy],[sy, cy]]
        // m = Ry*Rx:
        // m00 = cy*cx + (-sy)*(-i sx) = (cy*cx, sy*sx)
        // m01 = cy*(-i sx) + (-sy)*cx = (-sy*cx, -cy*sx)
        // m10 = sy*cx + cy*(-i sx)    = (sy*cx, -cy*sx)
        // m11 = sy*(-i sx) + cy*cx    = (cy*cx, -sy*sx)
        const float2 A00 = make_float2(cya * cxa,  sya * sxa);
        const float2 A01 = make_float2(-sya * cxa, -cya * sxa);
        const float2 A10 = make_float2( sya * cxa, -cya * sxa);
        const float2 A11 = make_float2(cya * cxa, -sya * sxa);
        const float2 eza  = make_float2(cza, -sza);
        const float2 ezac = make_float2(cza,  sza);
        const float2 ua00 = cmul(eza,  A00), ua01 = cmul(eza,  A01);
        const float2 ua10 = cmul(ezac, A10), ua11 = cmul(ezac, A11);

        const float2 B00 = make_float2(cyb * cxb,  syb * sxb);
        const float2 B01 = make_float2(-syb * cxb, -cyb * sxb);
        const float2 B10 = make_float2( syb * cxb, -cyb * sxb);
        const float2 B11 = make_float2(cyb * cxb, -syb * sxb);
        const float2 ezb  = make_float2(czb, -szb);
        const float2 ezbc = make_float2(czb,  szb);
        const float2 ub00 = cmul(ezb,  B00), ub01 = cmul(ezb,  B01);
        const float2 ub10 = cmul(ezbc, B10), ub11 = cmul(ezbc, B11);

        const int ba = 7 - qa, bb = 7 - qb;
        const int ma = 1 << ba, mb = 1 << bb;
        const int ra = (tid >> ba) & 1, rb = (tid >> bb) & 1;
        const int base = tid & ~(ma | mb);

        const float2 ka0 = ra ? ua10 : ua00;
        const float2 ka1 = ra ? ua11 : ua01;
        const float2 kb0 = rb ? ub10 : ub00;
        const float2 kb1 = rb ? ub11 : ub01;

        const float2 c00 = cmul(ka0, kb0);
        const float2 c01 = cmul(ka0, kb1);
        const float2 c10 = cmul(ka1, kb0);
        const float2 c11 = cmul(ka1, kb1);

        float2 r = cmul(c00, buf[cp][base]);
        r = cmad(r, c01, buf[cp][base | mb]);
        r = cmad(r, c10, buf[cp][base | ma]);
        r = cmad(r, c11, buf[cp][base | ma | mb]);
        buf[cp ^ 1][tid] = r;
        __syncthreads();
        cp ^= 1;
    }

    // ---- ising_xx, fused pairs sharing qubit i (16 steps)
#pragma unroll 1
    for (int gidx = 0; gidx < 16; gidx++) {
        const int i  = GI_[gidx];
        const int j1 = GJ1_[gidx];
        const int j2 = GJ2_[gidx];
        const int m1 = (1 << (7 - i)) | (1 << (7 - j1));
        float s1, c1;
        __sincosf(0.5f * scpl[i * 8 + j1], &s1, &c1);
        float2 r;
        const float2 A = buf[cp][tid];
        const float2 B = buf[cp][tid ^ m1];
        if (j2 == 255) {
            r = make_float2(c1 * A.x + s1 * B.y,
                            c1 * A.y - s1 * B.x);
        } else {
            const int m2 = (1 << (7 - i)) | (1 << (7 - j2));
            float s2, c2;
            __sincosf(0.5f * scpl[i * 8 + j2], &s2, &c2);
            const float2 C = buf[cp][tid ^ m2];
            const float2 D = buf[cp][tid ^ m1 ^ m2];
            const float cc = c1 * c2, sc = s1 * c2, cs = c1 * s2, ssn = s1 * s2;
            r = make_float2(cc * A.x + sc * B.y + cs * C.y - ssn * D.x,
                            cc * A.y - sc * B.x - cs * C.x - ssn * D.y);
        }
        buf[cp ^ 1][tid] = r;
        __syncthreads();
        cp ^= 1;
    }

    // ---- fused conv+pool applies (uniform predicate)
#pragma unroll 1
    for (int p = 0; p < 28; p++) {
        if ((amask >> p) & 1u) {
            const int bi = 7 - PI_[p];
            const int bj = 7 - PJ_[p];
            const int mi = 1 << bi, mj = 1 << bj;
            const int row  = (((tid >> bi) & 1) << 1) | ((tid >> bj) & 1);
            const int base = tid & ~(mi | mj);
            const float2* Mp = &pairM[p][row * 4];
            float2 r = cmul(Mp[0], buf[cp][base]);
            r = cmad(r, Mp[1], buf[cp][base | mj]);
            r = cmad(r, Mp[2], buf[cp][base | mi]);
            r = cmad(r, Mp[3], buf[cp][base | mi | mj]);
            buf[cp ^ 1][tid] = r;
            __syncthreads();
            cp ^= 1;
        }
    }

    g_psi[tid] = buf[cp][tid];

    if (!write_out) return;

    // ---- outer product, real part, written directly from this block.
    // thread owns 4 fixed columns; loops over rows in chunks of 4.
    const int q  = tid & 63;
    const int c0 = q << 2;
    const float2 b0 = buf[cp][c0];
    const float2 b1 = buf[cp][c0 + 1];
    const float2 b2 = buf[cp][c0 + 2];
    const float2 b3 = buf[cp][c0 + 3];
    const int rsub = tid >> 6;
#pragma unroll 4
    for (int it = 0; it < 64; it++) {
        const int r = (it << 2) | rsub;
        const float2 a = buf[cp][r];
        float4 o;
        o.x = a.x * b0.x + a.y * b0.y;
        o.y = a.x * b1.x + a.y * b1.y;
        o.z = a.x * b2.x + a.y * b2.y;
        o.w = a.x * b3.x + a.y * b3.y;
        out[(r << 6) + q] = o;
    }
}

// fallback for unexpected out_size (planar [Re|Im])
__global__ void __launch_bounds__(256)
outer_planar_kernel(float* __restrict__ out) {
    const int r = blockIdx.x;
    const int c = threadIdx.x;
    const float2 a = g_psi[r];
    const float2 b = g_psi[c];
    out[r * DIM + c]             = a.x * b.x + a.y * b.y;
    out[DIM * DIM + r * DIM + c] = a.y * b.x - a.x * b.y;
}

extern "C" void kernel_launch(void* const* d_in, const int* in_sizes, int n_in,
                              void* d_out, int out_size) {
    const float* x   = nullptr;
    const float* w   = nullptr;
    const float* cpl = nullptr;
    for (int i = 0; i < n_in; i++) {
        if      (in_sizes[i] == 256) x   = (const float*)d_in[i];
        else if (in_sizes[i] == 210) w   = (const float*)d_in[i];
        else if (in_sizes[i] == 64)  cpl = (const float*)d_in[i];
    }

    const int real_only = (out_size == DIM * DIM);
    fused_kernel<<<1, 256>>>(x, w, cpl, (float4*)d_out, real_only);
    if (!real_only) {
        outer_planar_kernel<<<DIM, DIM>>>((float*)d_out);
    }
}